// round 9
// baseline (speedup 1.0000x reference)
#include <cuda_runtime.h>
#include <cstdint>
#include <cstddef>

// LocalConvolution via warp-level bf16 split MMA (mma.sync m16n8k16),
// WARP-SPECIALIZED: 8 consumer warps (MMA only) + 4 producer warps
// (W LDG -> hi/lo bf16 convert -> STS, P dense copies), double-buffered smem,
// full/empty mbarrier pairs. Prep kernel pre-splits x to [c,h,w][b] bf16 hi/lo.
// Per CTA (pos): D[o=128, b=64] = W[128,K] @ P[64,K]^T, K = 1600.

#define B_  64
#define C_  64
#define H_  32
#define W_  32
#define CC  28
#define O_  128
#define K_  1600
#define KT  64
#define NTILES 25
#define NPOS 784
#define CHW (C_*H_*W_)        // 65536

// per-buffer smem layout: bf16 tiles, 144B padded rows
#define ROWB 144
#define WHI_OFF 0
#define WLO_OFF (128*ROWB)                 // 18432
#define PHI_OFF (2*128*ROWB)               // 36864
#define PLO_OFF (2*128*ROWB + 64*ROWB)     // 46080
#define BUFSZ   (2*128*ROWB + 2*64*ROWB)   // 55296
#define MBAR_OFF (2*BUFSZ)                 // 110592: full0, empty0, full1, empty1
#define SMEM_TOTAL (2*BUFSZ + 64)          // 110656

#define NPROD_THREADS 128
#define NCONS_THREADS 256

__device__ uint4 g_xhi[CHW * B_ * 2 / 16];
__device__ uint4 g_xlo[CHW * B_ * 2 / 16];

__device__ __forceinline__ uint32_t smem_u32(const void* p) {
    uint32_t a;
    asm("{ .reg .u64 t; cvta.to.shared.u64 t, %1; cvt.u32.u64 %0, t; }" : "=r"(a) : "l"(p));
    return a;
}

__device__ __forceinline__ uint32_t cvt2(float flo, float fhi) {
    uint32_t r;
    asm("cvt.rn.bf16x2.f32 %0, %1, %2;" : "=r"(r) : "f"(fhi), "f"(flo));
    return r;
}

__device__ __forceinline__ void ldsm4(uint32_t* r, uint32_t addr) {
    asm volatile("ldmatrix.sync.aligned.m8n8.x4.shared.b16 {%0,%1,%2,%3}, [%4];"
                 : "=r"(r[0]), "=r"(r[1]), "=r"(r[2]), "=r"(r[3]) : "r"(addr));
}

__device__ __forceinline__ void ldsm4t(uint32_t* r, uint32_t addr) {
    asm volatile("ldmatrix.sync.aligned.m8n8.x4.trans.shared.b16 {%0,%1,%2,%3}, [%4];"
                 : "=r"(r[0]), "=r"(r[1]), "=r"(r[2]), "=r"(r[3]) : "r"(addr));
}

__device__ __forceinline__ void mma16816(float* d, const uint32_t* a, uint32_t b0, uint32_t b1) {
    asm volatile(
        "mma.sync.aligned.m16n8k16.row.col.f32.bf16.bf16.f32 "
        "{%0,%1,%2,%3}, {%4,%5,%6,%7}, {%8,%9}, {%0,%1,%2,%3};"
        : "+f"(d[0]), "+f"(d[1]), "+f"(d[2]), "+f"(d[3])
        : "r"(a[0]), "r"(a[1]), "r"(a[2]), "r"(a[3]), "r"(b0), "r"(b1));
}

__device__ __forceinline__ void mbar_init(uint32_t mbar, uint32_t cnt) {
    asm volatile("mbarrier.init.shared.b64 [%0], %1;" :: "r"(mbar), "r"(cnt) : "memory");
}

__device__ __forceinline__ void mbar_arrive(uint32_t mbar) {
    asm volatile("mbarrier.arrive.shared.b64 _, [%0];" :: "r"(mbar) : "memory");
}

__device__ __forceinline__ void mbar_wait(uint32_t mbar, uint32_t parity) {
    asm volatile(
        "{\n\t.reg .pred P1;\n"
        "WAIT_%=:\n\t"
        "mbarrier.try_wait.parity.acquire.cta.shared::cta.b64 P1, [%0], %1, 0x989680;\n\t"
        "@P1 bra.uni DONE_%=;\n\t"
        "bra.uni WAIT_%=;\n"
        "DONE_%=:\n\t}"
        :: "r"(mbar), "r"(parity) : "memory");
}

// ---- prep: x[b][chw] f32 -> g_xhi/g_xlo [chw][b] bf16 (hi/lo RN split) ----
__global__ __launch_bounds__(256)
void prep_kernel(const float* __restrict__ x) {
    __shared__ float ts[B_][65];
    const int tid = threadIdx.x;
    const int wid = tid >> 5;
    const int lane = tid & 31;
    const int chw0 = blockIdx.x * 64;

    #pragma unroll
    for (int bi = 0; bi < 8; bi++) {
        int b = wid * 8 + bi;
        const float* xp = x + (size_t)b * CHW + chw0;
        ts[b][lane]      = xp[lane];
        ts[b][lane + 32] = xp[lane + 32];
    }
    __syncthreads();

    const int chw_l = tid >> 2;
    const int bc = tid & 3;
    uint32_t hi[8], lo[8];
    #pragma unroll
    for (int p = 0; p < 8; p++) {
        float f0 = ts[bc * 16 + p * 2][chw_l];
        float f1 = ts[bc * 16 + p * 2 + 1][chw_l];
        uint32_t h = cvt2(f0, f1);
        float l0 = f0 - __uint_as_float(h << 16);
        float l1 = f1 - __uint_as_float(h & 0xffff0000u);
        hi[p] = h;
        lo[p] = cvt2(l0, l1);
    }
    char* oh = (char*)g_xhi + (size_t)(chw0 + chw_l) * 128 + bc * 32;
    char* ol = (char*)g_xlo + (size_t)(chw0 + chw_l) * 128 + bc * 32;
    *(uint4*)oh        = make_uint4(hi[0], hi[1], hi[2], hi[3]);
    *(uint4*)(oh + 16) = make_uint4(hi[4], hi[5], hi[6], hi[7]);
    *(uint4*)ol        = make_uint4(lo[0], lo[1], lo[2], lo[3]);
    *(uint4*)(ol + 16) = make_uint4(lo[4], lo[5], lo[6], lo[7]);
}

// ---- main kernel: 384 threads = 8 consumer warps + 4 producer warps ----
__global__ __launch_bounds__(384, 2)
void lc_hmma_kernel(const float* __restrict__ x,
                    const float* __restrict__ w,
                    float* __restrict__ out) {
    extern __shared__ char smem[];
    const uint32_t sbase = smem_u32(smem);

    const int tid = threadIdx.x;
    const int wid = tid >> 5;
    const int l   = tid & 31;

    const int pos = blockIdx.x;
    const int i = pos / CC;
    const int j = pos - i * CC;

    // mbarriers: full0, empty0, full1, empty1 (8B each)
    const uint32_t mFull0  = sbase + MBAR_OFF;
    const uint32_t mEmpty0 = sbase + MBAR_OFF + 8;
    const uint32_t mFull1  = sbase + MBAR_OFF + 16;
    const uint32_t mEmpty1 = sbase + MBAR_OFF + 24;
    if (tid == 0) {
        mbar_init(mFull0,  NPROD_THREADS);
        mbar_init(mEmpty0, NCONS_THREADS);
        mbar_init(mFull1,  NPROD_THREADS);
        mbar_init(mEmpty1, NCONS_THREADS);
    }
    __syncthreads();

    if (wid < 8) {
        // ================= CONSUMERS =================
        const int o0 = (wid >> 1) * 32;
        const int b0 = (wid & 1) * 32;
        const uint32_t aRowRel = (uint32_t)((o0 + (l & 15)) * ROWB + (l >> 4) * 16);
        const uint32_t bRowRel = (uint32_t)(PHI_OFF + (((l >> 3) & 1) * 8 + (l & 7)) * ROWB
                                            + (b0 + (l >> 4) * 8) * 2);

        float acc[2][4][4];
        #pragma unroll
        for (int mi = 0; mi < 2; mi++)
            #pragma unroll
            for (int bt = 0; bt < 4; bt++)
                #pragma unroll
                for (int c = 0; c < 4; c++) acc[mi][bt][c] = 0.0f;

        #pragma unroll 1
        for (int t = 0; t < NTILES; t++) {
            const int stage = t & 1;
            const uint32_t phase = (uint32_t)((t >> 1) & 1);
            mbar_wait(stage ? mFull1 : mFull0, phase);

            const uint32_t bufOff = (uint32_t)stage * BUFSZ;
            const uint32_t aRow = sbase + bufOff + aRowRel;
            const uint32_t bRow = sbase + bufOff + bRowRel;
            #pragma unroll
            for (int ks = 0; ks < 4; ks++) {
                const uint32_t aCol = (uint32_t)ks * 32;
                const uint32_t bOff = (uint32_t)ks * 16 * ROWB;
                uint32_t ah[2][4], al[2][4];
                ldsm4(ah[0], aRow + aCol);
                ldsm4(ah[1], aRow + aCol + 16 * ROWB);
                ldsm4(al[0], aRow + aCol + (WLO_OFF - WHI_OFF));
                ldsm4(al[1], aRow + aCol + (WLO_OFF - WHI_OFF) + 16 * ROWB);
                #pragma unroll
                for (int g = 0; g < 2; g++) {
                    uint32_t bh[4], bl[4];
                    ldsm4t(bh, bRow + bOff + g * 32);
                    ldsm4t(bl, bRow + bOff + (PLO_OFF - PHI_OFF) + g * 32);
                    #pragma unroll
                    for (int mi = 0; mi < 2; mi++) {
                        #pragma unroll
                        for (int p = 0; p < 2; p++) {
                            float* d = acc[mi][g * 2 + p];
                            mma16816(d, ah[mi], bh[p * 2], bh[p * 2 + 1]);
                            mma16816(d, ah[mi], bl[p * 2], bl[p * 2 + 1]);
                            mma16816(d, al[mi], bh[p * 2], bh[p * 2 + 1]);
                        }
                    }
                }
            }
            mbar_arrive(stage ? mEmpty1 : mEmpty0);
        }

        // epilogue
        const int orow = l >> 2;
        const int bcol = (l & 3) * 2;
        #pragma unroll
        for (int mi = 0; mi < 2; mi++) {
            #pragma unroll
            for (int bt = 0; bt < 4; bt++) {
                #pragma unroll
                for (int c = 0; c < 4; c++) {
                    int o = o0 + mi * 16 + orow + (c >> 1) * 8;
                    int b = b0 + bt * 8 + bcol + (c & 1);
                    out[((size_t)b * O_ + o) * NPOS + pos] = acc[mi][bt][c];
                }
            }
        }
    } else {
        // ================= PRODUCERS =================
        const int ptid = tid - NCONS_THREADS;            // 0..127
        const float* __restrict__ wbase = w + (size_t)pos * (O_ * K_);
        const int kr = ptid >> 1;                        // P k-row 0..63
        const int half = ptid & 1;                       // 64B half of the b row

        #pragma unroll 1
        for (int t = 0; t < NTILES; t++) {
            const int stage = t & 1;
            const uint32_t phase = (uint32_t)(((t >> 1) & 1) ^ 1);  // producer parity
            mbar_wait(stage ? mEmpty1 : mEmpty0, phase);

            const uint32_t bufOff = (uint32_t)stage * BUFSZ;
            const float* wt = wbase + t * KT;

            // W tile: 2048 float4 chunks, 16 per producer thread
            #pragma unroll 4
            for (int ci = 0; ci < 16; ci++) {
                int ch = ptid + ci * 128;
                int o = ch >> 4, kc = ch & 15;
                float4 f = *(const float4*)(wt + (size_t)o * K_ + kc * 4);
                uint32_t h01 = cvt2(f.x, f.y);
                uint32_t h23 = cvt2(f.z, f.w);
                float lo0 = f.x - __uint_as_float(h01 << 16);
                float lo1 = f.y - __uint_as_float(h01 & 0xffff0000u);
                float lo2 = f.z - __uint_as_float(h23 << 16);
                float lo3 = f.w - __uint_as_float(h23 & 0xffff0000u);
                uint32_t l01 = cvt2(lo0, lo1);
                uint32_t l23 = cvt2(lo2, lo3);
                uint32_t off = bufOff + (uint32_t)o * ROWB + (uint32_t)kc * 8;
                *(uint2*)(smem + WHI_OFF + off) = make_uint2(h01, h23);
                *(uint2*)(smem + WLO_OFF + off) = make_uint2(l01, l23);
            }

            // P tile: k-row kr, this thread's 64B half (hi + lo)
            {
                int kg = t * KT + kr;
                int c = kg / 25;
                int rem = kg - c * 25;
                int u = rem / 5;
                int v = rem - u * 5;
                size_t sp = ((size_t)(c * (H_ * W_) + (i + u) * W_ + (j + v))) * 128
                          + (size_t)half * 64;
                uint4 h0 = *(const uint4*)((const char*)g_xhi + sp);
                uint4 h1 = *(const uint4*)((const char*)g_xhi + sp + 16);
                uint4 h2 = *(const uint4*)((const char*)g_xhi + sp + 32);
                uint4 h3 = *(const uint4*)((const char*)g_xhi + sp + 48);
                uint4 l0 = *(const uint4*)((const char*)g_xlo + sp);
                uint4 l1 = *(const uint4*)((const char*)g_xlo + sp + 16);
                uint4 l2 = *(const uint4*)((const char*)g_xlo + sp + 32);
                uint4 l3 = *(const uint4*)((const char*)g_xlo + sp + 48);
                char* dh = smem + PHI_OFF + bufOff + kr * ROWB + half * 64;
                char* dl = smem + PLO_OFF + bufOff + kr * ROWB + half * 64;
                *(uint4*)(dh)      = h0;
                *(uint4*)(dh + 16) = h1;
                *(uint4*)(dh + 32) = h2;
                *(uint4*)(dh + 48) = h3;
                *(uint4*)(dl)      = l0;
                *(uint4*)(dl + 16) = l1;
                *(uint4*)(dl + 32) = l2;
                *(uint4*)(dl + 48) = l3;
            }

            mbar_arrive(stage ? mFull1 : mFull0);
        }
    }
}

extern "C" void kernel_launch(void* const* d_in, const int* in_sizes, int n_in,
                              void* d_out, int out_size) {
    const float* x;
    const float* w;
    if (in_sizes[0] == B_ * C_ * H_ * W_) {
        x = (const float*)d_in[0];
        w = (const float*)d_in[1];
    } else {
        x = (const float*)d_in[1];
        w = (const float*)d_in[0];
    }
    float* out = (float*)d_out;
    prep_kernel<<<CHW / 64, 256>>>(x);
    cudaFuncSetAttribute(lc_hmma_kernel, cudaFuncAttributeMaxDynamicSharedMemorySize, SMEM_TOTAL);
    lc_hmma_kernel<<<NPOS, 384, SMEM_TOTAL>>>(x, w, out);
}

// round 10
// speedup vs baseline: 1.3517x; 1.3517x over previous
#include <cuda_runtime.h>
#include <cstdint>
#include <cstddef>

// LocalConvolution via warp-level bf16 split MMA (mma.sync m16n8k16).
// R10: cp.async multistage pipeline. W tiles land in smem as RAW F32 via
// cp.async (no register staging, no producer warps); consumers build bf16
// hi/lo A-fragments inline from f32 smem (LDS.64 + cvt), hiding the convert
// under the tensor-serialized HMMA issue slots. P is pre-split bf16 hi/lo
// ([c,h,w][b] layout) copied gmem->smem by cp.async.
// Per CTA (pos): D[o=128, b=64] = W[128,K] @ P[64,K]^T, K = 1600.

#define B_  64
#define C_  64
#define H_  32
#define W_  32
#define CC  28
#define O_  128
#define K_  1600
#define KT  64
#define NTILES 25
#define NPOS 784
#define CHW (C_*H_*W_)        // 65536

// per-stage smem: W f32 [128 rows][72 floats = 288B] + P bf16 hi/lo [64][144B]
#define WROWB 288
#define PROWB 144
#define WST_OFF 0                     // 128*288 = 36864
#define PHI_OFF 36864                 // 64*144  = 9216
#define PLO_OFF (36864 + 9216)        // 46080
#define STAGESZ (36864 + 2*9216)      // 55296
#define SMEM_TOTAL (2*STAGESZ)        // 110592

__device__ uint4 g_xhi[CHW * B_ * 2 / 16];
__device__ uint4 g_xlo[CHW * B_ * 2 / 16];

__device__ __forceinline__ uint32_t smem_u32(const void* p) {
    uint32_t a;
    asm("{ .reg .u64 t; cvta.to.shared.u64 t, %1; cvt.u32.u64 %0, t; }" : "=r"(a) : "l"(p));
    return a;
}

__device__ __forceinline__ uint32_t cvt2(float flo, float fhi) {
    uint32_t r;
    asm("cvt.rn.bf16x2.f32 %0, %1, %2;" : "=r"(r) : "f"(fhi), "f"(flo));
    return r;
}

__device__ __forceinline__ void cp16(uint32_t smem_dst, const void* gmem_src) {
    asm volatile("cp.async.cg.shared.global [%0], [%1], 16;"
                 :: "r"(smem_dst), "l"(__cvta_generic_to_global(gmem_src)) : "memory");
}

__device__ __forceinline__ float2 lds64(uint32_t addr) {
    float2 v;
    asm volatile("ld.shared.v2.f32 {%0,%1}, [%2];" : "=f"(v.x), "=f"(v.y) : "r"(addr));
    return v;
}

__device__ __forceinline__ void ldsm4t(uint32_t* r, uint32_t addr) {
    asm volatile("ldmatrix.sync.aligned.m8n8.x4.trans.shared.b16 {%0,%1,%2,%3}, [%4];"
                 : "=r"(r[0]), "=r"(r[1]), "=r"(r[2]), "=r"(r[3]) : "r"(addr));
}

__device__ __forceinline__ void mma16816(float* d, const uint32_t* a, uint32_t b0, uint32_t b1) {
    asm volatile(
        "mma.sync.aligned.m16n8k16.row.col.f32.bf16.bf16.f32 "
        "{%0,%1,%2,%3}, {%4,%5,%6,%7}, {%8,%9}, {%0,%1,%2,%3};"
        : "+f"(d[0]), "+f"(d[1]), "+f"(d[2]), "+f"(d[3])
        : "r"(a[0]), "r"(a[1]), "r"(a[2]), "r"(a[3]), "r"(b0), "r"(b1));
}

// ---- prep: x[b][chw] f32 -> g_xhi/g_xlo [chw][b] bf16 (hi/lo RN split) ----
__global__ __launch_bounds__(256)
void prep_kernel(const float* __restrict__ x) {
    __shared__ float ts[B_][65];
    const int tid = threadIdx.x;
    const int wid = tid >> 5;
    const int lane = tid & 31;
    const int chw0 = blockIdx.x * 64;

    #pragma unroll
    for (int bi = 0; bi < 8; bi++) {
        int b = wid * 8 + bi;
        const float* xp = x + (size_t)b * CHW + chw0;
        ts[b][lane]      = xp[lane];
        ts[b][lane + 32] = xp[lane + 32];
    }
    __syncthreads();

    const int chw_l = tid >> 2;
    const int bc = tid & 3;
    uint32_t hi[8], lo[8];
    #pragma unroll
    for (int p = 0; p < 8; p++) {
        float f0 = ts[bc * 16 + p * 2][chw_l];
        float f1 = ts[bc * 16 + p * 2 + 1][chw_l];
        uint32_t h = cvt2(f0, f1);
        float l0 = f0 - __uint_as_float(h << 16);
        float l1 = f1 - __uint_as_float(h & 0xffff0000u);
        hi[p] = h;
        lo[p] = cvt2(l0, l1);
    }
    char* oh = (char*)g_xhi + (size_t)(chw0 + chw_l) * 128 + bc * 32;
    char* ol = (char*)g_xlo + (size_t)(chw0 + chw_l) * 128 + bc * 32;
    *(uint4*)oh        = make_uint4(hi[0], hi[1], hi[2], hi[3]);
    *(uint4*)(oh + 16) = make_uint4(hi[4], hi[5], hi[6], hi[7]);
    *(uint4*)ol        = make_uint4(lo[0], lo[1], lo[2], lo[3]);
    *(uint4*)(ol + 16) = make_uint4(lo[4], lo[5], lo[6], lo[7]);
}

// ---- main kernel ----
__global__ __launch_bounds__(256, 2)
void lc_hmma_kernel(const float* __restrict__ x,
                    const float* __restrict__ w,
                    float* __restrict__ out) {
    extern __shared__ char smem[];
    const uint32_t sbase = smem_u32(smem);

    const int tid = threadIdx.x;
    const int wid = tid >> 5;
    const int l   = tid & 31;

    const int pos = blockIdx.x;
    const int i = pos / CC;
    const int j = pos - i * CC;
    const float* __restrict__ wbase = w + (size_t)pos * (O_ * K_);

    const int o0 = (wid >> 1) * 32;
    const int b0 = (wid & 1) * 32;

    // ---- cp.async stage fill for tile t into stage s ----
    auto stage_fill = [&](int t, int s) {
        const uint32_t stOff = sbase + (uint32_t)s * STAGESZ;
        // W: 128 rows x 64 floats -> 2048 x 16B granules, 8 per thread
        const float* wt = wbase + t * KT;
        #pragma unroll
        for (int ci = 0; ci < 8; ci++) {
            int idx = tid + ci * 256;
            int row = idx >> 4;
            int g16 = idx & 15;
            cp16(stOff + WST_OFF + row * WROWB + g16 * 16,
                 wt + (size_t)row * K_ + g16 * 4);
        }
        // P: hi+lo, 64 rows x 128B -> 1024 x 16B granules, 4 per thread
        #pragma unroll
        for (int ci = 0; ci < 4; ci++) {
            int idx = tid + ci * 256;
            int half = idx >> 9;
            int row = (idx >> 3) & 63;
            int g8 = idx & 7;
            int kg = t * KT + row;
            int c = kg / 25;
            int rem = kg - c * 25;
            int u = rem / 5;
            int v = rem - u * 5;
            size_t sp = ((size_t)(c * (H_ * W_) + (i + u) * W_ + (j + v))) * 128 + g8 * 16;
            const char* src = (half ? (const char*)g_xlo : (const char*)g_xhi) + sp;
            cp16(stOff + (half ? PLO_OFF : PHI_OFF) + row * PROWB + g8 * 16, src);
        }
        asm volatile("cp.async.commit_group;" ::: "memory");
    };

    // B-frag lane address (relative to stage base)
    const uint32_t bRowRel = (uint32_t)(PHI_OFF + (((l >> 3) & 1) * 8 + (l & 7)) * PROWB
                                        + (b0 + (l >> 4) * 8) * 2);
    // A f32 lane base: row = o0 + (l>>2), col = (l&3)*2
    const uint32_t aBaseRel = (uint32_t)(WST_OFF + (o0 + (l >> 2)) * WROWB + (l & 3) * 8);

    float acc[2][4][4];
    #pragma unroll
    for (int mi = 0; mi < 2; mi++)
        #pragma unroll
        for (int bt = 0; bt < 4; bt++)
            #pragma unroll
            for (int c = 0; c < 4; c++) acc[mi][bt][c] = 0.0f;

    // ---- prologue: start tiles 0 and 1 ----
    stage_fill(0, 0);
    stage_fill(1, 1);

    #pragma unroll 1
    for (int t = 0; t < NTILES; t++) {
        if (t == NTILES - 1) {
            asm volatile("cp.async.wait_group 0;" ::: "memory");
        } else {
            asm volatile("cp.async.wait_group 1;" ::: "memory");
        }
        __syncthreads();

        const uint32_t stOff = sbase + (uint32_t)(t & 1) * STAGESZ;
        const uint32_t aBase = stOff + aBaseRel;
        const uint32_t bRow  = stOff + bRowRel;

        #pragma unroll
        for (int ks = 0; ks < 4; ks++) {
            // ---- A fragments (hi+lo) from f32 smem ----
            uint32_t ah[2][4], al[2][4];
            #pragma unroll
            for (int mi = 0; mi < 2; mi++) {
                const uint32_t rbase = aBase + (uint32_t)(mi * 16) * WROWB + (uint32_t)(ks * 64);
                #pragma unroll
                for (int q = 0; q < 4; q++) {
                    // q: (row+8*(q&1), col+8*(q>>1))
                    uint32_t addr = rbase + (uint32_t)((q & 1) * 8) * WROWB
                                          + (uint32_t)((q >> 1) * 32);
                    float2 f = lds64(addr);
                    uint32_t h = cvt2(f.x, f.y);
                    float h0 = __uint_as_float(h << 16);
                    float h1 = __uint_as_float(h & 0xffff0000u);
                    ah[mi][q] = h;
                    al[mi][q] = cvt2(f.x - h0, f.y - h1);
                }
            }
            // ---- B fragments + MMAs ----
            const uint32_t bOff = (uint32_t)ks * 16 * PROWB;
            #pragma unroll
            for (int g = 0; g < 2; g++) {
                uint32_t bh[4], bl[4];
                ldsm4t(bh, bRow + bOff + g * 32);
                ldsm4t(bl, bRow + bOff + (PLO_OFF - PHI_OFF) + g * 32);
                #pragma unroll
                for (int mi = 0; mi < 2; mi++) {
                    #pragma unroll
                    for (int p = 0; p < 2; p++) {
                        float* d = acc[mi][g * 2 + p];
                        mma16816(d, ah[mi], bh[p * 2], bh[p * 2 + 1]);
                        mma16816(d, ah[mi], bl[p * 2], bl[p * 2 + 1]);
                        mma16816(d, al[mi], bh[p * 2], bh[p * 2 + 1]);
                    }
                }
            }
        }
        __syncthreads();

        if (t + 2 < NTILES) stage_fill(t + 2, t & 1);
    }

    // ---- epilogue: o = o0+mi*16+(l>>2)+8*(c>>1), b = b0+bt*8+(l&3)*2+(c&1)
    const int orow = l >> 2;
    const int bcol = (l & 3) * 2;
    #pragma unroll
    for (int mi = 0; mi < 2; mi++) {
        #pragma unroll
        for (int bt = 0; bt < 4; bt++) {
            #pragma unroll
            for (int c = 0; c < 4; c++) {
                int o = o0 + mi * 16 + orow + (c >> 1) * 8;
                int b = b0 + bt * 8 + bcol + (c & 1);
                out[((size_t)b * O_ + o) * NPOS + pos] = acc[mi][bt][c];
            }
        }
    }
}

extern "C" void kernel_launch(void* const* d_in, const int* in_sizes, int n_in,
                              void* d_out, int out_size) {
    const float* x;
    const float* w;
    if (in_sizes[0] == B_ * C_ * H_ * W_) {
        x = (const float*)d_in[0];
        w = (const float*)d_in[1];
    } else {
        x = (const float*)d_in[1];
        w = (const float*)d_in[0];
    }
    float* out = (float*)d_out;
    prep_kernel<<<CHW / 64, 256>>>(x);
    cudaFuncSetAttribute(lc_hmma_kernel, cudaFuncAttributeMaxDynamicSharedMemorySize, SMEM_TOTAL);
    lc_hmma_kernel<<<NPOS, 256, SMEM_TOTAL>>>(x, w, out);
}